// round 16
// baseline (speedup 1.0000x reference)
#include <cuda_runtime.h>
#include <cuda_bf16.h>
#include <math.h>
#include <stdint.h>

#define T_TASKS 64
#define B_ROWS  4096
#define TD      512
#define HD      256
#define VD      484
#define VDP     512
#define BM      64
#define NBLK    (B_ROWS / BM)   // 64

// ---- smem byte offsets ----
#define OFF_RED 0        // 516 floats
#define OFF_B1  2176
#define OFF_GM  3200
#define OFF_BT  4224
#define OFF_B2  5248
#define OFF_CT  7200     // ends 9136
// GEMM1 staging: KC=64, row stride 144 B, double buffered, bf16.
#define G1_BUF(b) (9216 + (b) * 46080)     // ends 101376
#define G1_A  0
#define G1_B  9216
// H (post-GELU bf16 [64][256], row stride 528 B) — reuses G1 region after GEMM1
#define HS    9216       // 64*528 = 33792 -> ends 43008
// GEMM2 W2 staging: KC=128, row stride 272 B, double buffered (after HS)
#define W2_BUF(b) (43008 + (b) * 34816)    // ends 112640
#define SMEM_BYTES 112640                   // 2 CTAs/SM: 225280 <= 227KB

// ---- precomputed bf16 operands ----
#define TF_PAIRS  ((size_t)B_ROWS * TD / 2)
#define W1_PAIRS  ((size_t)T_TASKS * HD * TD / 2)
#define W2_PAIRS  ((size_t)T_TASKS * VDP * HD / 2)
#define CVT_TOTAL (TF_PAIRS + W1_PAIRS + W2_PAIRS)
#define CVT_BLOCKS ((int)((CVT_TOTAL / 2 + 255) / 256))
__device__ uint4 g_tf_h[TF_PAIRS / 4];
__device__ uint4 g_w1_h[W1_PAIRS / 4];
__device__ uint4 g_w2_h[W2_PAIRS / 4];
__device__ float g_partial[T_TASKS * NBLK];
__device__ float g_cnorm[T_TASKS];

__device__ __forceinline__ uint32_t smem_u32(const void* p) {
    uint32_t a;
    asm("{ .reg .u64 t; cvta.to.shared.u64 t, %1; cvt.u32.u64 %0, t; }" : "=r"(a) : "l"(p));
    return a;
}
__device__ __forceinline__ void ldsm4(uint32_t* r, uint32_t addr) {
    asm volatile("ldmatrix.sync.aligned.m8n8.x4.shared.b16 {%0,%1,%2,%3}, [%4];"
        : "=r"(r[0]), "=r"(r[1]), "=r"(r[2]), "=r"(r[3]) : "r"(addr));
}
__device__ __forceinline__ void mma16816(float* d, const uint32_t* a, const uint32_t* b) {
    asm volatile("mma.sync.aligned.m16n8k16.row.col.f32.bf16.bf16.f32 "
        "{%0,%1,%2,%3}, {%4,%5,%6,%7}, {%8,%9}, {%0,%1,%2,%3};"
        : "+f"(d[0]), "+f"(d[1]), "+f"(d[2]), "+f"(d[3])
        : "r"(a[0]), "r"(a[1]), "r"(a[2]), "r"(a[3]), "r"(b[0]), "r"(b[1]));
}
__device__ __forceinline__ void cpa16(uint32_t dst, const void* src) {
    asm volatile("cp.async.cg.shared.global [%0], [%1], 16;" :: "r"(dst), "l"(src));
}
#define CP_COMMIT() asm volatile("cp.async.commit_group;" ::: "memory")
#define CP_WAIT0()  asm volatile("cp.async.wait_group 0;" ::: "memory")

__device__ __forceinline__ unsigned pack_bf16x2(float x0, float x1) {
    __nv_bfloat16 h0 = __float2bfloat16(x0), h1 = __float2bfloat16(x1);
    return ((unsigned)__bfloat16_as_ushort(h1) << 16) | __bfloat16_as_ushort(h0);
}

// ---------------------------------------------------------------------------
// convert (+ fused centroid norms): tf/W1/W2 -> bf16; last 64 blocks do cnorm
// ---------------------------------------------------------------------------
__global__ void convert_kernel(const float* __restrict__ tf,
                               const float* __restrict__ W1,
                               const float* __restrict__ W2,
                               const float* __restrict__ cent) {
    if (blockIdx.x >= CVT_BLOCKS) {            // centroid-norm blocks
        int t = blockIdx.x - CVT_BLOCKS;
        float s = 0.f;
        for (int n = threadIdx.x; n < VD; n += 256) {
            float c = cent[(size_t)t * VD + n];
            s = fmaf(c, c, s);
        }
#pragma unroll
        for (int o = 16; o > 0; o >>= 1) s += __shfl_xor_sync(0xffffffffu, s, o);
        __shared__ float ws[8];
        if ((threadIdx.x & 31) == 0) ws[threadIdx.x >> 5] = s;
        __syncthreads();
        if (threadIdx.x == 0) {
            float tot = 0.f;
#pragma unroll
            for (int i = 0; i < 8; i++) tot += ws[i];
            g_cnorm[t] = fmaxf(sqrtf(tot), 1e-8f);
        }
        return;
    }
    size_t p = ((size_t)blockIdx.x * blockDim.x + threadIdx.x) * 2;
    if (p >= CVT_TOTAL) return;
    uint2 o;
    if (p < TF_PAIRS) {
        float4 v = *reinterpret_cast<const float4*>(tf + 2 * p);
        o.x = pack_bf16x2(v.x, v.y); o.y = pack_bf16x2(v.z, v.w);
        *reinterpret_cast<uint2*>((unsigned*)g_tf_h + p) = o;
    } else if (p < TF_PAIRS + W1_PAIRS) {
        size_t idx = p - TF_PAIRS;
        float4 v = *reinterpret_cast<const float4*>(W1 + 2 * idx);
        o.x = pack_bf16x2(v.x, v.y); o.y = pack_bf16x2(v.z, v.w);
        *reinterpret_cast<uint2*>((unsigned*)g_w1_h + idx) = o;
    } else {
        size_t idx0 = p - TF_PAIRS - W1_PAIRS;
        size_t per_task = (size_t)VDP * HD / 2;
        unsigned res[2];
#pragma unroll
        for (int j = 0; j < 2; j++) {
            size_t idx = idx0 + j;
            size_t t = idx / per_task, r = idx % per_task;
            size_t n = r / (HD / 2), k2 = r % (HD / 2);
            float x0 = 0.f, x1 = 0.f;
            if (n < VD) {
                const float* s = W2 + t * (size_t)VD * HD + n * HD + 2 * k2;
                x0 = s[0]; x1 = s[1];
            }
            res[j] = pack_bf16x2(x0, x1);
        }
        o.x = res[0]; o.y = res[1];
        *reinterpret_cast<uint2*>((unsigned*)g_w2_h + idx0) = o;
    }
}

// ---------------------------------------------------------------------------
// fused HMMA router: BM=64, 256 thr (2x4 warp grid), 2 CTAs/SM, W2 KC=128
// ---------------------------------------------------------------------------
__global__ __launch_bounds__(256, 2)
void router_mma(const float* __restrict__ b1v, const float* __restrict__ gamma,
                const float* __restrict__ beta, const float* __restrict__ b2v,
                const float* __restrict__ cent) {
    extern __shared__ char smem[];
    const uint32_t sbase = smem_u32(smem);
    const int tid = threadIdx.x;
    const int w = tid >> 5, l = tid & 31;
    const int wr = w & 1, wc = w >> 1;      // 2 row groups x 4 col groups
    const int m0 = wr * 32;
    const int g  = l >> 2, q4 = l & 3;
    const int t = blockIdx.y;
    const int brow0 = blockIdx.x * BM;

    float* red = (float*)(smem + OFF_RED);
    float* b1s = (float*)(smem + OFF_B1);
    float* gms = (float*)(smem + OFF_GM);
    float* bts = (float*)(smem + OFF_BT);
    float* b2s = (float*)(smem + OFF_B2);
    float* cts = (float*)(smem + OFF_CT);

    if (tid < HD) {
        b1s[tid] = b1v[t * HD + tid];
        gms[tid] = gamma[t * HD + tid];
        bts[tid] = beta[t * HD + tid];
    }
    for (int i = tid; i < VD; i += 256) {
        b2s[i] = b2v[(size_t)t * VD + i];
        cts[i] = cent[(size_t)t * VD + i];
    }

    const int a_mrow = ((l >> 3) & 1) * 8 + (l & 7);
    const int a_kh   = (l >> 4) * 16;
    const int b_nrow = (l >> 4) * 8 + (l & 7);
    const int b_kh   = ((l >> 3) & 1) * 16;

    // ---- staging (cp.async) ----
    auto stage_g1 = [&](int c, int b) {                   // KC=64
        uint32_t base = sbase + G1_BUF(b);
#pragma unroll
        for (int q = tid; q < 512; q += 256) {            // A: 64 rows x 8 uint4
            int r = q >> 3, i = q & 7;
            size_t gi = (size_t)(brow0 + r) * 64 + (size_t)c * 8 + i;
            cpa16(base + G1_A + r * 144 + i * 16, &g_tf_h[gi]);
        }
#pragma unroll
        for (int q = tid; q < 2048; q += 256) {           // B=W1: 256 rows x 8 uint4
            int r = q >> 3, i = q & 7;
            size_t gi = (size_t)t * 16384 + (size_t)r * 64 + (size_t)c * 8 + i;
            cpa16(base + G1_B + r * 144 + i * 16, &g_w1_h[gi]);
        }
    };
    auto stage_w2 = [&](int u, int b) {                   // u = nt*2 + kc, KC=128
        int nt = u >> 1, kc = u & 1;
        uint32_t base = sbase + W2_BUF(b);
#pragma unroll
        for (int q = tid; q < 2048; q += 256) {           // 128 rows x 16 uint4
            int r = q >> 4, i = q & 15;
            size_t gi = (size_t)t * 16384 + (size_t)(nt * 128 + r) * 32 + (size_t)kc * 16 + i;
            cpa16(base + r * 272 + i * 16, &g_w2_h[gi]);
        }
    };

    // ===================== GEMM1 (8 chunks of KC=64) =======================
    float acc[2][8][4];
#pragma unroll
    for (int mi = 0; mi < 2; mi++)
#pragma unroll
        for (int ni = 0; ni < 8; ni++)
#pragma unroll
            for (int e = 0; e < 4; e++) acc[mi][ni][e] = 0.f;

    stage_g1(0, 0);
    CP_COMMIT();
    for (int c = 0; c < 8; c++) {
        const int b = c & 1;
        CP_WAIT0();
        __syncthreads();
        if (c < 7) { stage_g1(c + 1, b ^ 1); CP_COMMIT(); }
        uint32_t abase = sbase + G1_BUF(b);
#pragma unroll
        for (int kk = 0; kk < 4; kk++) {
            const int kb = kk * 32;
            uint32_t ah[2][4];
#pragma unroll
            for (int mi = 0; mi < 2; mi++) {
                int ro = (m0 + mi * 16 + a_mrow) * 144 + kb + a_kh;
                ldsm4(ah[mi], abase + G1_A + ro);
            }
#pragma unroll
            for (int p = 0; p < 4; p++) {
                int ro = (wc * 64 + p * 16 + b_nrow) * 144 + kb + b_kh;
                uint32_t bh[4];
                ldsm4(bh, abase + G1_B + ro);
#pragma unroll
                for (int mi = 0; mi < 2; mi++)
#pragma unroll
                    for (int e = 0; e < 2; e++)
                        mma16816(acc[mi][p * 2 + e], ah[mi], bh + e * 2);
            }
        }
    }
    __syncthreads();   // all warps done with G1 buffers before W2/HS overwrite

    stage_w2(0, 0);
    CP_COMMIT();

    // ======= epilogue 1: bias + LayerNorm + GELU -> H bf16 smem ============
    {
        float s[4] = {0, 0, 0, 0}, s2[4] = {0, 0, 0, 0};
#pragma unroll
        for (int mi = 0; mi < 2; mi++)
#pragma unroll
            for (int ni = 0; ni < 8; ni++) {
                int col = wc * 64 + ni * 8 + q4 * 2;
                float bb0 = b1s[col], bb1 = b1s[col + 1];
                float* C = acc[mi][ni];
                C[0] += bb0; C[1] += bb1; C[2] += bb0; C[3] += bb1;
                s[mi * 2 + 0] += C[0] + C[1];
                s2[mi * 2 + 0] = fmaf(C[0], C[0], fmaf(C[1], C[1], s2[mi * 2 + 0]));
                s[mi * 2 + 1] += C[2] + C[3];
                s2[mi * 2 + 1] = fmaf(C[2], C[2], fmaf(C[3], C[3], s2[mi * 2 + 1]));
            }
#pragma unroll
        for (int sl = 0; sl < 4; sl++)
#pragma unroll
            for (int o = 1; o < 4; o <<= 1) {
                s[sl]  += __shfl_xor_sync(0xffffffffu, s[sl], o);
                s2[sl] += __shfl_xor_sync(0xffffffffu, s2[sl], o);
            }
        if (q4 == 0) {
#pragma unroll
            for (int sl = 0; sl < 4; sl++) {
                int r = m0 + (sl >> 1) * 16 + (sl & 1) * 8 + g;
                red[wc * 64 + r] = s[sl];
                red[256 + wc * 64 + r] = s2[sl];
            }
        }
        __syncthreads();
        float mu[4], rs[4];
#pragma unroll
        for (int sl = 0; sl < 4; sl++) {
            int r = m0 + (sl >> 1) * 16 + (sl & 1) * 8 + g;
            float ts  = red[r] + red[64 + r] + red[128 + r] + red[192 + r];
            float ts2 = red[256 + r] + red[320 + r] + red[384 + r] + red[448 + r];
            mu[sl] = ts * (1.f / HD);
            rs[sl] = rsqrtf(ts2 * (1.f / HD) - mu[sl] * mu[sl] + 1e-5f);
        }
        __syncthreads();
#pragma unroll
        for (int mi = 0; mi < 2; mi++)
#pragma unroll
            for (int ni = 0; ni < 8; ni++) {
                int col = wc * 64 + ni * 8 + q4 * 2;
                float gm0 = gms[col], gm1 = gms[col + 1];
                float bt0 = bts[col], bt1 = bts[col + 1];
                float* C = acc[mi][ni];
#pragma unroll
                for (int rh = 0; rh < 2; rh++) {
                    int sl = mi * 2 + rh;
                    int r = m0 + mi * 16 + rh * 8 + g;
                    float y0 = (C[rh * 2 + 0] - mu[sl]) * rs[sl] * gm0 + bt0;
                    float y1 = (C[rh * 2 + 1] - mu[sl]) * rs[sl] * gm1 + bt1;
                    float g0 = 0.5f * y0 * (1.f + erff(y0 * 0.70710678118654752f));
                    float g1 = 0.5f * y1 * (1.f + erff(y1 * 0.70710678118654752f));
                    *(unsigned*)(smem + HS + r * 528 + col * 2) = pack_bf16x2(g0, g1);
                }
            }
    }
    __syncthreads();

    // ===== GEMM2: 8 chunks (4 nt x 2 kc of K=128); warp tile 32x32 =========
    float num[4] = {0, 0, 0, 0}, sq[4] = {0, 0, 0, 0};
    float acc2[2][4][4];
    for (int u = 0; u < 8; u++) {
        const int b = u & 1, kc = u & 1, nt = u >> 1;
        CP_WAIT0();
        __syncthreads();
        if (u < 7) { stage_w2(u + 1, b ^ 1); CP_COMMIT(); }
        if (kc == 0) {
#pragma unroll
            for (int mi = 0; mi < 2; mi++)
#pragma unroll
                for (int ni = 0; ni < 4; ni++)
#pragma unroll
                    for (int e = 0; e < 4; e++) acc2[mi][ni][e] = 0.f;
        }
        const bool lastw = (nt == 3) && (wc == 3);   // cols 480..511 this warp
        uint32_t wbase = sbase + W2_BUF(b);
#pragma unroll
        for (int kk = 0; kk < 8; kk++) {
            const int kb = kk * 32;
            uint32_t ah[2][4];
#pragma unroll
            for (int mi = 0; mi < 2; mi++) {
                int ro = (m0 + mi * 16 + a_mrow) * 528 + kc * 256 + kb + a_kh;
                ldsm4(ah[mi], sbase + HS + ro);
            }
#pragma unroll
            for (int p = 0; p < 2; p++) {
                if (lastw && p == 1) continue;               // cols 496..511: all pad
                int ro = (wc * 32 + p * 16 + b_nrow) * 272 + kb + b_kh;
                uint32_t bh[4];
                ldsm4(bh, wbase + ro);
#pragma unroll
                for (int e = 0; e < 2; e++) {
                    if (lastw && p == 0 && e == 1) continue; // cols 488..495: all pad
#pragma unroll
                    for (int mi = 0; mi < 2; mi++)
                        mma16816(acc2[mi][p * 2 + e], ah[mi], bh + e * 2);
                }
            }
        }
        if (kc == 1) {   // fold v = acc2 + b2 into cosine sums
#pragma unroll
            for (int mi = 0; mi < 2; mi++)
#pragma unroll
                for (int ni = 0; ni < 4; ni++) {
                    int col = nt * 128 + wc * 32 + ni * 8 + q4 * 2;
                    if (col < VD) {
                        float bb0 = b2s[col], bb1 = b2s[col + 1];
                        float cc0 = cts[col], cc1 = cts[col + 1];
                        float* C = acc2[mi][ni];
#pragma unroll
                        for (int rh = 0; rh < 2; rh++) {
                            int sl = mi * 2 + rh;
                            float v0 = C[rh * 2 + 0] + bb0;
                            float v1 = C[rh * 2 + 1] + bb1;
                            num[sl] = fmaf(v0, cc0, fmaf(v1, cc1, num[sl]));
                            sq[sl]  = fmaf(v0, v0, fmaf(v1, v1, sq[sl]));
                        }
                    }
                }
        }
    }

    // ================= per-row cosine, block partial =======================
#pragma unroll
    for (int sl = 0; sl < 4; sl++)
#pragma unroll
        for (int o = 1; o < 4; o <<= 1) {
            num[sl] += __shfl_xor_sync(0xffffffffu, num[sl], o);
            sq[sl]  += __shfl_xor_sync(0xffffffffu, sq[sl], o);
        }
    __syncthreads();
    if (q4 == 0) {
#pragma unroll
        for (int sl = 0; sl < 4; sl++) {
            int r = m0 + (sl >> 1) * 16 + (sl & 1) * 8 + g;
            red[wc * 64 + r] = num[sl];
            red[256 + wc * 64 + r] = sq[sl];
        }
    }
    __syncthreads();
    float rd = 0.f;
    if (wc == 0 && q4 == 0) {
        float cn = g_cnorm[t];
#pragma unroll
        for (int sl = 0; sl < 4; sl++) {
            int r = m0 + (sl >> 1) * 16 + (sl & 1) * 8 + g;
            float nu = red[r] + red[64 + r] + red[128 + r] + red[192 + r];
            float sv = red[256 + r] + red[320 + r] + red[384 + r] + red[448 + r];
            float vn = fmaxf(sqrtf(sv), 1e-8f);
            rd += 1.f - nu / (vn * cn);
        }
    }
#pragma unroll
    for (int o = 16; o > 0; o >>= 1) rd += __shfl_xor_sync(0xffffffffu, rd, o);
    if (wc == 0 && l == 0) red[512 + wr] = rd;
    __syncthreads();
    if (tid == 0)
        g_partial[t * NBLK + blockIdx.x] = red[512] + red[513];
}

__global__ void finalize_kernel(float* __restrict__ out, int out_size) {
    __shared__ float dist[T_TASKS];
    int t = threadIdx.x;
    if (t < T_TASKS) {
        float s = 0.f;
#pragma unroll
        for (int b = 0; b < NBLK; b++) s += g_partial[t * NBLK + b];
        float d = s * (1.0f / (float)B_ROWS);
        dist[t] = d;
        if (out_size >= T_TASKS) out[t] = d;
    }
    __syncthreads();
    if (t == 0) {
        int best = 0; float bv = dist[0];
        for (int i = 1; i < T_TASKS; i++)
            if (dist[i] < bv) { bv = dist[i]; best = i; }
        if (out_size >= T_TASKS + 1)      out[T_TASKS] = (float)best;
        else if (out_size >= 1 && out_size < T_TASKS) out[0] = (float)best;
    }
}

extern "C" void kernel_launch(void* const* d_in, const int* in_sizes, int n_in,
                              void* d_out, int out_size) {
    const float* t_feat = (const float*)d_in[0];
    const float* W1     = (const float*)d_in[1];
    const float* b1     = (const float*)d_in[2];
    const float* gamma  = (const float*)d_in[3];
    const float* beta   = (const float*)d_in[4];
    const float* W2     = (const float*)d_in[5];
    const float* b2     = (const float*)d_in[6];
    const float* cent   = (const float*)d_in[7];

    cudaFuncSetAttribute(router_mma, cudaFuncAttributeMaxDynamicSharedMemorySize, SMEM_BYTES);

    convert_kernel<<<CVT_BLOCKS + T_TASKS, 256>>>(t_feat, W1, W2, cent);
    dim3 grid(NBLK, T_TASKS);
    router_mma<<<grid, 256, SMEM_BYTES>>>(b1, gamma, beta, b2, cent);
    finalize_kernel<<<1, 64>>>((float*)d_out, out_size);
}

// round 17
// speedup vs baseline: 1.0252x; 1.0252x over previous
#include <cuda_runtime.h>
#include <cuda_bf16.h>
#include <math.h>
#include <stdint.h>

#define T_TASKS 64
#define B_ROWS  4096
#define TD      512
#define HD      256
#define VD      484
#define VDP     512
#define BM      64
#define NBLK    (B_ROWS / BM)   // 64

// ---- smem byte offsets (R15 layout) ----
#define OFF_RED 0        // 516 floats
#define OFF_B1  2176
#define OFF_GM  3200
#define OFF_BT  4224
#define OFF_B2  5248
#define OFF_CT  7200     // ends 9136
// GEMM1 staging: KC=64, row stride 144 B, double buffered, bf16.
#define G1_BUF(b) (9216 + (b) * 46080)     // ends 101376
#define G1_A  0
#define G1_B  9216
// H (post-GELU bf16 [64][256], row stride 528 B) — reuses G1 region after GEMM1
#define HS    9216       // 64*528 = 33792 -> ends 43008
// GEMM2 W2 staging: KC=64, row stride 144 B, double buffered (after HS)
#define W2_BUF(b) (43008 + (b) * 18432)    // ends 79872
#define SMEM_BYTES 101376                   // 2 CTAs/SM

// ---- precomputed bf16 operands ----
#define TF_PAIRS  ((size_t)B_ROWS * TD / 2)
#define W1_PAIRS  ((size_t)T_TASKS * HD * TD / 2)
#define W2_PAIRS  ((size_t)T_TASKS * VDP * HD / 2)
#define CVT_TOTAL (TF_PAIRS + W1_PAIRS + W2_PAIRS)
#define CVT_BLOCKS ((int)((CVT_TOTAL / 2 + 255) / 256))
__device__ uint4 g_tf_h[TF_PAIRS / 4];
__device__ uint4 g_w1_h[W1_PAIRS / 4];
__device__ uint4 g_w2_h[W2_PAIRS / 4];
__device__ float g_partial[T_TASKS * NBLK];
__device__ float g_cnorm[T_TASKS];

__device__ __forceinline__ uint32_t smem_u32(const void* p) {
    uint32_t a;
    asm("{ .reg .u64 t; cvta.to.shared.u64 t, %1; cvt.u32.u64 %0, t; }" : "=r"(a) : "l"(p));
    return a;
}
__device__ __forceinline__ void ldsm4(uint32_t* r, uint32_t addr) {
    asm volatile("ldmatrix.sync.aligned.m8n8.x4.shared.b16 {%0,%1,%2,%3}, [%4];"
        : "=r"(r[0]), "=r"(r[1]), "=r"(r[2]), "=r"(r[3]) : "r"(addr));
}
__device__ __forceinline__ void mma16816(float* d, const uint32_t* a, const uint32_t* b) {
    asm volatile("mma.sync.aligned.m16n8k16.row.col.f32.bf16.bf16.f32 "
        "{%0,%1,%2,%3}, {%4,%5,%6,%7}, {%8,%9}, {%0,%1,%2,%3};"
        : "+f"(d[0]), "+f"(d[1]), "+f"(d[2]), "+f"(d[3])
        : "r"(a[0]), "r"(a[1]), "r"(a[2]), "r"(a[3]), "r"(b[0]), "r"(b[1]));
}
__device__ __forceinline__ void cpa16(uint32_t dst, const void* src) {
    asm volatile("cp.async.cg.shared.global [%0], [%1], 16;" :: "r"(dst), "l"(src));
}
#define CP_COMMIT() asm volatile("cp.async.commit_group;" ::: "memory")
#define CP_WAIT0()  asm volatile("cp.async.wait_group 0;" ::: "memory")

__device__ __forceinline__ unsigned pack_bf16x2(float x0, float x1) {
    __nv_bfloat16 h0 = __float2bfloat16(x0), h1 = __float2bfloat16(x1);
    return ((unsigned)__bfloat16_as_ushort(h1) << 16) | __bfloat16_as_ushort(h0);
}

// ---------------------------------------------------------------------------
// convert (+ fused centroid norms): tf/W1/W2 -> bf16; last 64 blocks do cnorm
// ---------------------------------------------------------------------------
__global__ void convert_kernel(const float* __restrict__ tf,
                               const float* __restrict__ W1,
                               const float* __restrict__ W2,
                               const float* __restrict__ cent) {
    if (blockIdx.x >= CVT_BLOCKS) {            // centroid-norm blocks
        int t = blockIdx.x - CVT_BLOCKS;
        float s = 0.f;
        for (int n = threadIdx.x; n < VD; n += 256) {
            float c = cent[(size_t)t * VD + n];
            s = fmaf(c, c, s);
        }
#pragma unroll
        for (int o = 16; o > 0; o >>= 1) s += __shfl_xor_sync(0xffffffffu, s, o);
        __shared__ float ws[8];
        if ((threadIdx.x & 31) == 0) ws[threadIdx.x >> 5] = s;
        __syncthreads();
        if (threadIdx.x == 0) {
            float tot = 0.f;
#pragma unroll
            for (int i = 0; i < 8; i++) tot += ws[i];
            g_cnorm[t] = fmaxf(sqrtf(tot), 1e-8f);
        }
        return;
    }
    size_t p = ((size_t)blockIdx.x * blockDim.x + threadIdx.x) * 2;
    if (p >= CVT_TOTAL) return;
    uint2 o;
    if (p < TF_PAIRS) {
        float4 v = *reinterpret_cast<const float4*>(tf + 2 * p);
        o.x = pack_bf16x2(v.x, v.y); o.y = pack_bf16x2(v.z, v.w);
        *reinterpret_cast<uint2*>((unsigned*)g_tf_h + p) = o;
    } else if (p < TF_PAIRS + W1_PAIRS) {
        size_t idx = p - TF_PAIRS;
        float4 v = *reinterpret_cast<const float4*>(W1 + 2 * idx);
        o.x = pack_bf16x2(v.x, v.y); o.y = pack_bf16x2(v.z, v.w);
        *reinterpret_cast<uint2*>((unsigned*)g_w1_h + idx) = o;
    } else {
        size_t idx0 = p - TF_PAIRS - W1_PAIRS;
        size_t per_task = (size_t)VDP * HD / 2;
        unsigned res[2];
#pragma unroll
        for (int j = 0; j < 2; j++) {
            size_t idx = idx0 + j;
            size_t t = idx / per_task, r = idx % per_task;
            size_t n = r / (HD / 2), k2 = r % (HD / 2);
            float x0 = 0.f, x1 = 0.f;
            if (n < VD) {
                const float* s = W2 + t * (size_t)VD * HD + n * HD + 2 * k2;
                x0 = s[0]; x1 = s[1];
            }
            res[j] = pack_bf16x2(x0, x1);
        }
        o.x = res[0]; o.y = res[1];
        *reinterpret_cast<uint2*>((unsigned*)g_w2_h + idx0) = o;
    }
}

// ---------------------------------------------------------------------------
// fused HMMA router: BM=64, 256 thr (2x4 warp grid), 2 CTAs/SM  (R15 mainloop)
// ---------------------------------------------------------------------------
__global__ __launch_bounds__(256, 2)
void router_mma(const float* __restrict__ b1v, const float* __restrict__ gamma,
                const float* __restrict__ beta, const float* __restrict__ b2v,
                const float* __restrict__ cent) {
    extern __shared__ char smem[];
    const uint32_t sbase = smem_u32(smem);
    const int tid = threadIdx.x;
    const int w = tid >> 5, l = tid & 31;
    const int wr = w & 1, wc = w >> 1;      // 2 row groups x 4 col groups
    const int m0 = wr * 32;
    const int g  = l >> 2, q4 = l & 3;
    const int t = blockIdx.y;
    const int brow0 = blockIdx.x * BM;

    float* red = (float*)(smem + OFF_RED);
    float* b1s = (float*)(smem + OFF_B1);
    float* gms = (float*)(smem + OFF_GM);
    float* bts = (float*)(smem + OFF_BT);
    float* b2s = (float*)(smem + OFF_B2);
    float* cts = (float*)(smem + OFF_CT);

    if (tid < HD) {
        b1s[tid] = b1v[t * HD + tid];
        gms[tid] = gamma[t * HD + tid];
        bts[tid] = beta[t * HD + tid];
    }
    for (int i = tid; i < VD; i += 256) {
        b2s[i] = b2v[(size_t)t * VD + i];
        cts[i] = cent[(size_t)t * VD + i];
    }

    const int a_mrow = ((l >> 3) & 1) * 8 + (l & 7);
    const int a_kh   = (l >> 4) * 16;
    const int b_nrow = (l >> 4) * 8 + (l & 7);
    const int b_kh   = ((l >> 3) & 1) * 16;

    // ---- staging (cp.async), KC=64 ----
    auto stage_g1 = [&](int c, int b) {
        uint32_t base = sbase + G1_BUF(b);
#pragma unroll
        for (int q = tid; q < 512; q += 256) {            // A: 64 rows x 8 uint4
            int r = q >> 3, i = q & 7;
            size_t gi = (size_t)(brow0 + r) * 64 + (size_t)c * 8 + i;
            cpa16(base + G1_A + r * 144 + i * 16, &g_tf_h[gi]);
        }
#pragma unroll
        for (int q = tid; q < 2048; q += 256) {           // B=W1: 256 rows x 8 uint4
            int r = q >> 3, i = q & 7;
            size_t gi = (size_t)t * 16384 + (size_t)r * 64 + (size_t)c * 8 + i;
            cpa16(base + G1_B + r * 144 + i * 16, &g_w1_h[gi]);
        }
    };
    auto stage_w2 = [&](int u, int b) {                   // u = nt*4 + c, KC=64
        int nt = u >> 2, c = u & 3;
        uint32_t base = sbase + W2_BUF(b);
#pragma unroll
        for (int q = tid; q < 1024; q += 256) {           // 128 rows x 8 uint4
            int r = q >> 3, i = q & 7;
            size_t gi = (size_t)t * 16384 + (size_t)(nt * 128 + r) * 32 + (size_t)c * 8 + i;
            cpa16(base + r * 144 + i * 16, &g_w2_h[gi]);
        }
    };

    // ===================== GEMM1 (8 chunks of KC=64) =======================
    float acc[2][8][4];
#pragma unroll
    for (int mi = 0; mi < 2; mi++)
#pragma unroll
        for (int ni = 0; ni < 8; ni++)
#pragma unroll
            for (int e = 0; e < 4; e++) acc[mi][ni][e] = 0.f;

    stage_g1(0, 0);
    CP_COMMIT();
    for (int c = 0; c < 8; c++) {
        const int b = c & 1;
        CP_WAIT0();
        __syncthreads();
        if (c < 7) { stage_g1(c + 1, b ^ 1); CP_COMMIT(); }
        uint32_t abase = sbase + G1_BUF(b);
#pragma unroll
        for (int kk = 0; kk < 4; kk++) {
            const int kb = kk * 32;
            uint32_t ah[2][4];
#pragma unroll
            for (int mi = 0; mi < 2; mi++) {
                int ro = (m0 + mi * 16 + a_mrow) * 144 + kb + a_kh;
                ldsm4(ah[mi], abase + G1_A + ro);
            }
#pragma unroll
            for (int p = 0; p < 4; p++) {
                int ro = (wc * 64 + p * 16 + b_nrow) * 144 + kb + b_kh;
                uint32_t bh[4];
                ldsm4(bh, abase + G1_B + ro);
#pragma unroll
                for (int mi = 0; mi < 2; mi++)
#pragma unroll
                    for (int e = 0; e < 2; e++)
                        mma16816(acc[mi][p * 2 + e], ah[mi], bh + e * 2);
            }
        }
    }
    __syncthreads();   // all warps done with G1 buffers before W2/HS overwrite

    stage_w2(0, 0);
    CP_COMMIT();

    // ======= epilogue 1: bias + LayerNorm + GELU -> H bf16 smem ============
    {
        float s[4] = {0, 0, 0, 0}, s2[4] = {0, 0, 0, 0};
#pragma unroll
        for (int mi = 0; mi < 2; mi++)
#pragma unroll
            for (int ni = 0; ni < 8; ni++) {
                int col = wc * 64 + ni * 8 + q4 * 2;
                float bb0 = b1s[col], bb1 = b1s[col + 1];
                float* C = acc[mi][ni];
                C[0] += bb0; C[1] += bb1; C[2] += bb0; C[3] += bb1;
                s[mi * 2 + 0] += C[0] + C[1];
                s2[mi * 2 + 0] = fmaf(C[0], C[0], fmaf(C[1], C[1], s2[mi * 2 + 0]));
                s[mi * 2 + 1] += C[2] + C[3];
                s2[mi * 2 + 1] = fmaf(C[2], C[2], fmaf(C[3], C[3], s2[mi * 2 + 1]));
            }
#pragma unroll
        for (int sl = 0; sl < 4; sl++)
#pragma unroll
            for (int o = 1; o < 4; o <<= 1) {
                s[sl]  += __shfl_xor_sync(0xffffffffu, s[sl], o);
                s2[sl] += __shfl_xor_sync(0xffffffffu, s2[sl], o);
            }
        if (q4 == 0) {
#pragma unroll
            for (int sl = 0; sl < 4; sl++) {
                int r = m0 + (sl >> 1) * 16 + (sl & 1) * 8 + g;
                red[wc * 64 + r] = s[sl];
                red[256 + wc * 64 + r] = s2[sl];
            }
        }
        __syncthreads();
        float mu[4], rs[4];
#pragma unroll
        for (int sl = 0; sl < 4; sl++) {
            int r = m0 + (sl >> 1) * 16 + (sl & 1) * 8 + g;
            float ts  = red[r] + red[64 + r] + red[128 + r] + red[192 + r];
            float ts2 = red[256 + r] + red[320 + r] + red[384 + r] + red[448 + r];
            mu[sl] = ts * (1.f / HD);
            rs[sl] = rsqrtf(ts2 * (1.f / HD) - mu[sl] * mu[sl] + 1e-5f);
        }
        __syncthreads();
#pragma unroll
        for (int mi = 0; mi < 2; mi++)
#pragma unroll
            for (int ni = 0; ni < 8; ni++) {
                int col = wc * 64 + ni * 8 + q4 * 2;
                float gm0 = gms[col], gm1 = gms[col + 1];
                float bt0 = bts[col], bt1 = bts[col + 1];
                float* C = acc[mi][ni];
#pragma unroll
                for (int rh = 0; rh < 2; rh++) {
                    int sl = mi * 2 + rh;
                    int r = m0 + mi * 16 + rh * 8 + g;
                    float y0 = (C[rh * 2 + 0] - mu[sl]) * rs[sl] * gm0 + bt0;
                    float y1 = (C[rh * 2 + 1] - mu[sl]) * rs[sl] * gm1 + bt1;
                    float g0 = 0.5f * y0 * (1.f + erff(y0 * 0.70710678118654752f));
                    float g1 = 0.5f * y1 * (1.f + erff(y1 * 0.70710678118654752f));
                    *(unsigned*)(smem + HS + r * 528 + col * 2) = pack_bf16x2(g0, g1);
                }
            }
    }
    __syncthreads();

    // ===== GEMM2: 16 chunks (4 nt x 4 c of K=64); warp tile 32x32 ==========
    float num[4] = {0, 0, 0, 0}, sq[4] = {0, 0, 0, 0};
    float acc2[2][4][4];
    for (int u = 0; u < 16; u++) {
        const int b = u & 1, c = u & 3, nt = u >> 2;
        CP_WAIT0();
        __syncthreads();
        if (u < 15) { stage_w2(u + 1, b ^ 1); CP_COMMIT(); }
        if (c == 0) {
#pragma unroll
            for (int mi = 0; mi < 2; mi++)
#pragma unroll
                for (int ni = 0; ni < 4; ni++)
#pragma unroll
                    for (int e = 0; e < 4; e++) acc2[mi][ni][e] = 0.f;
        }
        const bool lastw = (nt == 3) && (wc == 3);   // cols 480..511 this warp
        uint32_t wbase = sbase + W2_BUF(b);
#pragma unroll
        for (int kk = 0; kk < 4; kk++) {
            const int kb = kk * 32;
            uint32_t ah[2][4];
#pragma unroll
            for (int mi = 0; mi < 2; mi++) {
                int ro = (m0 + mi * 16 + a_mrow) * 528 + c * 128 + kb + a_kh;
                ldsm4(ah[mi], sbase + HS + ro);
            }
#pragma unroll
            for (int p = 0; p < 2; p++) {
                if (lastw && p == 1) continue;               // cols 496..511: all pad
                int ro = (wc * 32 + p * 16 + b_nrow) * 144 + kb + b_kh;
                uint32_t bh[4];
                ldsm4(bh, wbase + ro);
#pragma unroll
                for (int e = 0; e < 2; e++) {
                    if (lastw && p == 0 && e == 1) continue; // cols 488..495: all pad
#pragma unroll
                    for (int mi = 0; mi < 2; mi++)
                        mma16816(acc2[mi][p * 2 + e], ah[mi], bh + e * 2);
                }
            }
        }
        if (c == 3) {   // fold v = acc2 + b2 into cosine sums
#pragma unroll
            for (int mi = 0; mi < 2; mi++)
#pragma unroll
                for (int ni = 0; ni < 4; ni++) {
                    int col = nt * 128 + wc * 32 + ni * 8 + q4 * 2;
                    if (col < VD) {
                        float bb0 = b2s[col], bb1 = b2s[col + 1];
                        float cc0 = cts[col], cc1 = cts[col + 1];
                        float* C = acc2[mi][ni];
#pragma unroll
                        for (int rh = 0; rh < 2; rh++) {
                            int sl = mi * 2 + rh;
                            float v0 = C[rh * 2 + 0] + bb0;
                            float v1 = C[rh * 2 + 1] + bb1;
                            num[sl] = fmaf(v0, cc0, fmaf(v1, cc1, num[sl]));
                            sq[sl]  = fmaf(v0, v0, fmaf(v1, v1, sq[sl]));
                        }
                    }
                }
        }
    }

    // ================= per-row cosine, block partial =======================
#pragma unroll
    for (int sl = 0; sl < 4; sl++)
#pragma unroll
        for (int o = 1; o < 4; o <<= 1) {
            num[sl] += __shfl_xor_sync(0xffffffffu, num[sl], o);
            sq[sl]  += __shfl_xor_sync(0xffffffffu, sq[sl], o);
        }
    __syncthreads();
    if (q4 == 0) {
#pragma unroll
        for (int sl = 0; sl < 4; sl++) {
            int r = m0 + (sl >> 1) * 16 + (sl & 1) * 8 + g;
            red[wc * 64 + r] = num[sl];
            red[256 + wc * 64 + r] = sq[sl];
        }
    }
    __syncthreads();
    float rd = 0.f;
    if (wc == 0 && q4 == 0) {
        float cn = g_cnorm[t];
#pragma unroll
        for (int sl = 0; sl < 4; sl++) {
            int r = m0 + (sl >> 1) * 16 + (sl & 1) * 8 + g;
            float nu = red[r] + red[64 + r] + red[128 + r] + red[192 + r];
            float sv = red[256 + r] + red[320 + r] + red[384 + r] + red[448 + r];
            float vn = fmaxf(sqrtf(sv), 1e-8f);
            rd += 1.f - nu / (vn * cn);
        }
    }
#pragma unroll
    for (int o = 16; o > 0; o >>= 1) rd += __shfl_xor_sync(0xffffffffu, rd, o);
    if (wc == 0 && l == 0) red[512 + wr] = rd;
    __syncthreads();
    if (tid == 0)
        g_partial[t * NBLK + blockIdx.x] = red[512] + red[513];
}

__global__ void finalize_kernel(float* __restrict__ out, int out_size) {
    __shared__ float dist[T_TASKS];
    int t = threadIdx.x;
    if (t < T_TASKS) {
        float s = 0.f;
#pragma unroll
        for (int b = 0; b < NBLK; b++) s += g_partial[t * NBLK + b];
        float d = s * (1.0f / (float)B_ROWS);
        dist[t] = d;
        if (out_size >= T_TASKS) out[t] = d;
    }
    __syncthreads();
    if (t == 0) {
        int best = 0; float bv = dist[0];
        for (int i = 1; i < T_TASKS; i++)
            if (dist[i] < bv) { bv = dist[i]; best = i; }
        if (out_size >= T_TASKS + 1)      out[T_TASKS] = (float)best;
        else if (out_size >= 1 && out_size < T_TASKS) out[0] = (float)best;
    }
}

extern "C" void kernel_launch(void* const* d_in, const int* in_sizes, int n_in,
                              void* d_out, int out_size) {
    const float* t_feat = (const float*)d_in[0];
    const float* W1     = (const float*)d_in[1];
    const float* b1     = (const float*)d_in[2];
    const float* gamma  = (const float*)d_in[3];
    const float* beta   = (const float*)d_in[4];
    const float* W2     = (const float*)d_in[5];
    const float* b2     = (const float*)d_in[6];
    const float* cent   = (const float*)d_in[7];

    cudaFuncSetAttribute(router_mma, cudaFuncAttributeMaxDynamicSharedMemorySize, SMEM_BYTES);

    convert_kernel<<<CVT_BLOCKS + T_TASKS, 256>>>(t_feat, W1, W2, cent);
    dim3 grid(NBLK, T_TASKS);
    router_mma<<<grid, 256, SMEM_BYTES>>>(b1, gamma, beta, b2, cent);
    finalize_kernel<<<1, 64>>>((float*)d_out, out_size);
}